// round 3
// baseline (speedup 1.0000x reference)
#include <cuda_runtime.h>

#define NN 100000
#define NE 3200000
#define IND 512
#define HID 256
#define NC  64

// ---------------- scratch (static device globals; no runtime allocation) ----
__device__ float g_h1[(size_t)NN * HID];      // relu(x@W1+b1)   102.4 MB
__device__ float g_tb[3][(size_t)NN * NC];    // rotating T_k buffers, 25.6 MB each
__device__ int   g_rp[NN + 1];                // CSR row_ptr

// ---------------- row_ptr build: binary search per row over sorted edge_row -
__global__ void build_row_ptr(const int* __restrict__ erow) {
    int r = blockIdx.x * blockDim.x + threadIdx.x;
    if (r > NN) return;
    int lo = 0, hi = NE;
    while (lo < hi) {
        int mid = (lo + hi) >> 1;
        if (erow[mid] < r) lo = mid + 1; else hi = mid;
    }
    g_rp[r] = lo;
}

// ---------------- classic register-blocked SGEMM with bias (+optional relu) -
// A: MxK row-major, B: KxN row-major, C: MxN row-major. Guards only on M
// (N, K divisible by tile dims for our two shapes).
template <int BM, int BN, int BK, int TM, int TN, bool RELU>
__global__ void sgemm_bias(const float* __restrict__ A, const float* __restrict__ B,
                           const float* __restrict__ bias, float* __restrict__ C,
                           int M, int N, int K) {
    constexpr int THREADS = (BM / TM) * (BN / TN);
    __shared__ float As[BK][BM];
    __shared__ float Bs[BK][BN];

    const int tid = threadIdx.x;
    const int bm = blockIdx.y * BM;
    const int bn = blockIdx.x * BN;

    const int tx = tid % (BN / TN);
    const int ty = tid / (BN / TN);

    float acc[TM][TN];
#pragma unroll
    for (int i = 0; i < TM; ++i)
#pragma unroll
        for (int j = 0; j < TN; ++j) acc[i][j] = 0.f;

    // A-tile loader mapping (float4 along K)
    constexpr int A_ROWS_PER_PASS = THREADS / (BK / 4);
    constexpr int A_PASSES = BM / A_ROWS_PER_PASS;
    const int arow  = tid / (BK / 4);
    const int acol4 = tid % (BK / 4);

    // B-tile loader mapping (float4 along N)
    constexpr int B_ROWS_PER_PASS = THREADS / (BN / 4);
    constexpr int B_PASSES = BK / B_ROWS_PER_PASS;
    const int brow  = tid / (BN / 4);
    const int bcol4 = tid % (BN / 4);

    for (int k0 = 0; k0 < K; k0 += BK) {
#pragma unroll
        for (int p = 0; p < A_PASSES; ++p) {
            int r = arow + p * A_ROWS_PER_PASS;
            int grow = bm + r;
            float4 v = make_float4(0.f, 0.f, 0.f, 0.f);
            if (grow < M)
                v = *(const float4*)&A[(size_t)grow * K + k0 + acol4 * 4];
            As[acol4 * 4 + 0][r] = v.x;
            As[acol4 * 4 + 1][r] = v.y;
            As[acol4 * 4 + 2][r] = v.z;
            As[acol4 * 4 + 3][r] = v.w;
        }
#pragma unroll
        for (int p = 0; p < B_PASSES; ++p) {
            int r = brow + p * B_ROWS_PER_PASS;
            float4 v = *(const float4*)&B[(size_t)(k0 + r) * N + bn + bcol4 * 4];
            *(float4*)&Bs[r][bcol4 * 4] = v;
        }
        __syncthreads();

#pragma unroll
        for (int kk = 0; kk < BK; ++kk) {
            float ra[TM], rb[TN];
#pragma unroll
            for (int i = 0; i < TM; ++i) ra[i] = As[kk][ty * TM + i];
#pragma unroll
            for (int j = 0; j < TN; ++j) rb[j] = Bs[kk][tx * TN + j];
#pragma unroll
            for (int i = 0; i < TM; ++i)
#pragma unroll
                for (int j = 0; j < TN; ++j)
                    acc[i][j] = fmaf(ra[i], rb[j], acc[i][j]);
        }
        __syncthreads();
    }

#pragma unroll
    for (int i = 0; i < TM; ++i) {
        int grow = bm + ty * TM + i;
        if (grow >= M) continue;
#pragma unroll
        for (int j = 0; j < TN; j += 4) {
            int gcol = bn + tx * TN + j;
            float4 v;
            v.x = acc[i][j + 0] + bias[gcol + 0];
            v.y = acc[i][j + 1] + bias[gcol + 1];
            v.z = acc[i][j + 2] + bias[gcol + 2];
            v.w = acc[i][j + 3] + bias[gcol + 3];
            if (RELU) {
                v.x = fmaxf(v.x, 0.f); v.y = fmaxf(v.y, 0.f);
                v.z = fmaxf(v.z, 0.f); v.w = fmaxf(v.w, 0.f);
            }
            *(float4*)&C[(size_t)grow * N + gcol] = v;
        }
    }
}

// ---------------- fused CSR SpMM + Chebyshev recurrence ---------------------
// 16 threads per row, each owns 4 channels (float4). v-matrix rows are 64
// floats = 16 float4; gathers hit L2 (25.6 MB working set).
// first=1: t1 = spmm(h);            z  = g0*h + g1*t1
// else:    tn = 2*spmm(tc) - tp;    z += g[k]*tn
__global__ void spmm_cheb(const int* __restrict__ ecol, const float* __restrict__ evals,
                          const float* __restrict__ gamma, float* __restrict__ z,
                          int cur, int prev, int nxt, int k, int first) {
    int t = blockIdx.x * blockDim.x + threadIdx.x;
    int row = t >> 4;
    int c = t & 15;
    if (row >= NN) return;

    const float4* vcur = (const float4*)g_tb[cur];
    int s = g_rp[row];
    int e = g_rp[row + 1];

    float4 acc = make_float4(0.f, 0.f, 0.f, 0.f);
    for (int i = s; i < e; ++i) {
        int col = __ldg(ecol + i);
        float w = __ldg(evals + i);
        float4 v = __ldg(vcur + (size_t)col * 16 + c);
        acc.x = fmaf(w, v.x, acc.x);
        acc.y = fmaf(w, v.y, acc.y);
        acc.z = fmaf(w, v.z, acc.z);
        acc.w = fmaf(w, v.w, acc.w);
    }

    size_t o = (size_t)row * 16 + c;
    float4* vnext = (float4*)g_tb[nxt];
    float4* z4 = (float4*)z;

    if (first) {
        float g0 = gamma[0], g1 = gamma[1];
        float4 h = vcur[o];
        vnext[o] = acc;
        float4 zz;
        zz.x = g0 * h.x + g1 * acc.x;
        zz.y = g0 * h.y + g1 * acc.y;
        zz.z = g0 * h.z + g1 * acc.z;
        zz.w = g0 * h.w + g1 * acc.w;
        z4[o] = zz;
    } else {
        const float4* vprev = (const float4*)g_tb[prev];
        float4 p = vprev[o];
        float4 tn;
        tn.x = 2.f * acc.x - p.x;
        tn.y = 2.f * acc.y - p.y;
        tn.z = 2.f * acc.z - p.z;
        tn.w = 2.f * acc.w - p.w;
        vnext[o] = tn;
        float g = gamma[k];
        float4 zz = z4[o];
        zz.x = fmaf(g, tn.x, zz.x);
        zz.y = fmaf(g, tn.y, zz.y);
        zz.z = fmaf(g, tn.z, zz.z);
        zz.w = fmaf(g, tn.w, zz.w);
        z4[o] = zz;
    }
}

// ---------------- launch ----------------------------------------------------
extern "C" void kernel_launch(void* const* d_in, const int* in_sizes, int n_in,
                              void* d_out, int out_size) {
    const float* x     = (const float*)d_in[0];
    const int*   erow  = (const int*)d_in[1];
    const int*   ecol  = (const int*)d_in[2];
    const float* evals = (const float*)d_in[3];
    const float* W1    = (const float*)d_in[4];
    const float* b1    = (const float*)d_in[5];
    const float* W2    = (const float*)d_in[6];
    const float* b2    = (const float*)d_in[7];
    const float* gamma = (const float*)d_in[8];
    float* z = (float*)d_out;

    float* h1;
    float* tb0;
    cudaGetSymbolAddress((void**)&h1, g_h1);
    cudaGetSymbolAddress((void**)&tb0, g_tb);  // base of buffer 0

    // 1) h1 = relu(x @ W1 + b1)   [NN, HID]
    {
        dim3 grid(HID / 128, (NN + 127) / 128);
        sgemm_bias<128, 128, 8, 8, 8, true><<<grid, 256>>>(x, W1, b1, h1, NN, HID, IND);
    }
    // 2) h = h1 @ W2 + b2  -> g_tb[0]   [NN, NC]
    {
        dim3 grid(NC / 64, (NN + 127) / 128);
        sgemm_bias<128, 64, 16, 8, 4, false><<<grid, 256>>>(h1, W2, b2, tb0, NN, NC, HID);
    }
    // 3) CSR row_ptr
    build_row_ptr<<<(NN + 256) / 256, 256>>>(erow);

    // 4) Chebyshev chain (8 SpMMs, fused recurrence + z accumulation)
    const int SPMM_BLOCKS = (NN * 16 + 255) / 256;
    spmm_cheb<<<SPMM_BLOCKS, 256>>>(ecol, evals, gamma, z, /*cur=*/0, /*prev=*/0,
                                    /*nxt=*/1, /*k=*/1, /*first=*/1);
    int p = 0, c = 1;
    for (int k = 2; k <= 8; ++k) {
        int n = 3 - p - c;
        spmm_cheb<<<SPMM_BLOCKS, 256>>>(ecol, evals, gamma, z, c, p, n, k, 0);
        p = c; c = n;
    }
}

// round 5
// speedup vs baseline: 1.4129x; 1.4129x over previous
#include <cuda_runtime.h>
#include <cuda_bf16.h>
#include <cstdint>

#define NN 100000
#define ROWSP 100096           // NN padded to multiple of 128
#define NE 3200000
#define IND 512
#define HID 256
#define NC  64

// ---------------- scratch (static device globals; no runtime allocation) ----
__device__ float g_h1[(size_t)NN * HID];                       // relu(x@W1+b1), fp32
__device__ float g_tb[3][(size_t)NN * NC];                     // rotating T_k buffers
__device__ int   g_rp[NN + 1];                                 // CSR row_ptr
// A operand chunk-plane layout: [K/64 planes][ROWSP rows][64] bf16, SW128-swizzled
// per 128B row. Sized for K=512 (GEMM1); GEMM2 (K=256) reuses planes 0-3.
__device__ __align__(128) __nv_bfloat16 g_ahi[(size_t)8 * ROWSP * 64];
__device__ __align__(128) __nv_bfloat16 g_alo[(size_t)8 * ROWSP * 64];
// W operands, chunk-tiled [K/64][N][64] bf16 swizzled (B stored N-major, K contiguous)
__device__ __align__(128) __nv_bfloat16 g_w1hi[8 * 256 * 64], g_w1lo[8 * 256 * 64];
__device__ __align__(128) __nv_bfloat16 g_w2hi[4 * 64 * 64],  g_w2lo[4 * 64 * 64];

// ---------------- inline PTX helpers (base ISA only — no 'a' features) ------
__device__ __forceinline__ uint32_t smem_u32(const void* p) {
    uint32_t a;
    asm("{ .reg .u64 t; cvta.to.shared.u64 t, %1; cvt.u32.u64 %0, t; }" : "=r"(a) : "l"(p));
    return a;
}
#define MBARRIER_INIT(addr, cnt) \
    asm volatile("mbarrier.init.shared.b64 [%0], %1;" :: "r"(addr), "r"((uint32_t)(cnt)) : "memory")
#define MBARRIER_INVAL(addr) \
    asm volatile("mbarrier.inval.shared.b64 [%0];" :: "r"(addr) : "memory")
#define MBARRIER_EXPECT_TX(addr, bytes) \
    asm volatile("mbarrier.arrive.expect_tx.shared.b64 _, [%0], %1;" :: "r"(addr), "r"((uint32_t)(bytes)) : "memory")
__device__ __forceinline__ void mbar_wait(uint32_t mbar, uint32_t parity) {
    asm volatile(
        "{\n\t.reg .pred P1;\n\t"
        "WAIT_LOOP_%=:\n\t"
        "mbarrier.try_wait.parity.acquire.cta.shared::cta.b64 P1, [%0], %1, 0x989680;\n\t"
        "@P1 bra.uni WAIT_DONE_%=;\n\t"
        "bra.uni WAIT_LOOP_%=;\n\t"
        "WAIT_DONE_%=:\n\t}"
        :: "r"(mbar), "r"(parity) : "memory");
}
#define BULK_G2S(dst, src, bytes, mbar) \
    asm volatile("cp.async.bulk.shared::cta.global.mbarrier::complete_tx::bytes [%0], [%1], %2, [%3];" \
        :: "r"((uint32_t)(dst)), "l"(src), "r"((uint32_t)(bytes)), "r"((uint32_t)(mbar)) : "memory")

__device__ __forceinline__ void ldsm4(uint32_t* r, uint32_t addr) {
    asm volatile("ldmatrix.sync.aligned.m8n8.x4.shared.b16 {%0,%1,%2,%3}, [%4];"
        : "=r"(r[0]), "=r"(r[1]), "=r"(r[2]), "=r"(r[3]) : "r"(addr));
}
__device__ __forceinline__ void mma_bf16(float* d, const uint32_t* a, const uint32_t* b) {
    asm volatile("mma.sync.aligned.m16n8k16.row.col.f32.bf16.bf16.f32 "
        "{%0,%1,%2,%3}, {%4,%5,%6,%7}, {%8,%9}, {%0,%1,%2,%3};"
        : "+f"(d[0]), "+f"(d[1]), "+f"(d[2]), "+f"(d[3])
        : "r"(a[0]), "r"(a[1]), "r"(a[2]), "r"(a[3]), "r"(b[0]), "r"(b[1]));
}

// ---------------- prep kernels: fp32 -> bf16 hi/lo in swizzled chunk planes --
// A layout: plane c (K chunk of 64), row r, byte offset (kk*2) ^ ((r&7)<<4)
template <int KSHIFT>
__global__ void prep_a(const float* __restrict__ src,
                       __nv_bfloat16* __restrict__ dhi, __nv_bfloat16* __restrict__ dlo) {
    long long idx = (long long)blockIdx.x * blockDim.x + threadIdx.x;
    constexpr int K = 1 << KSHIFT;
    if (idx >= (long long)NN * K) return;
    int r = (int)(idx >> KSHIFT);
    int k = (int)idx & (K - 1);
    int c = k >> 6, kk = k & 63;
    float v = src[idx];
    __nv_bfloat16 hi = __float2bfloat16(v);
    __nv_bfloat16 lo = __float2bfloat16(v - __bfloat162float(hi));
    int poff = (kk << 1) ^ ((r & 7) << 4);
    size_t dst = ((size_t)c * ROWSP + r) * 64 + (poff >> 1);
    dhi[dst] = hi;
    dlo[dst] = lo;
}

// W layout: B[n][k] = W[k*N + n]; plane c, row n, perm (kk*2) ^ ((n&7)<<4)
template <int NSHIFT>
__global__ void prep_w(const float* __restrict__ src, int K,
                       __nv_bfloat16* __restrict__ dhi, __nv_bfloat16* __restrict__ dlo) {
    constexpr int N = 1 << NSHIFT;
    int idx = blockIdx.x * blockDim.x + threadIdx.x;
    if (idx >= K * N) return;
    int k = idx >> NSHIFT;
    int n = idx & (N - 1);
    int c = k >> 6, kk = k & 63;
    float v = src[idx];
    __nv_bfloat16 hi = __float2bfloat16(v);
    __nv_bfloat16 lo = __float2bfloat16(v - __bfloat162float(hi));
    int poff = (kk << 1) ^ ((n & 7) << 4);
    size_t dst = ((size_t)c * N + n) * 64 + (poff >> 1);
    dhi[dst] = hi;
    dlo[dst] = lo;
}

// ---------------- split-bf16 mma.sync GEMM ----------------------------------
// D[128, BN] tile = A[128, K] @ B[BN, K]^T, K consumed in NCHUNK chunks of 64.
// 3 split products per chunk: AhiBhi + AhiBlo + AloBhi (fp32 accumulate).
// 256 threads = 8 warps in WM x WN layout. cp.async.bulk double-buffered.
template <int BN, int NCHUNK, int WM, int WN, bool RELU>
__global__ void __launch_bounds__(256)
tc_gemm(const __nv_bfloat16* __restrict__ Ahi, const __nv_bfloat16* __restrict__ Alo,
        const __nv_bfloat16* __restrict__ Bhi, const __nv_bfloat16* __restrict__ Blo,
        const float* __restrict__ bias, float* __restrict__ C, int NB) {
    constexpr int WR = 128 / WM;           // rows per warp
    constexpr int WC = BN / WN;            // cols per warp
    constexpr int MT = WR / 16;            // 16-row mma tiles per warp
    constexpr int NT = WC / 8;             // 8-col mma tiles per warp (even)
    constexpr uint32_t BNB = BN * 128;     // B half-chunk bytes
    constexpr uint32_t BUFB = 32768 + 2 * BNB;
    constexpr uint32_t CHUNK_BYTES = BUFB;

    extern __shared__ char smem[];
    const uint32_t sb = smem_u32(smem);
    const int tid = threadIdx.x;
    const int lane = tid & 31;
    const int wid = tid >> 5;
    const int wm = wid / WN, wn = wid % WN;
    const int bm = blockIdx.x * 128;
    const int n0 = blockIdx.y * BN;

    const uint32_t mb0 = sb + 8, mb1 = sb + 16;
    if (tid == 0) { MBARRIER_INIT(mb0, 1); MBARRIER_INIT(mb1, 1); }
    __syncthreads();

    // prologue: issue loads for chunk 0 (buf0) and chunk 1 (buf1)
    if (tid == 0) {
#pragma unroll
        for (int c = 0; c < 2 && c < NCHUNK; ++c) {
            uint32_t mb = c ? mb1 : mb0;
            uint32_t base = sb + 1024 + c * BUFB;
            MBARRIER_EXPECT_TX(mb, CHUNK_BYTES);
            const char* ah = (const char*)Ahi + ((size_t)c * ROWSP + bm) * 128;
            const char* al = (const char*)Alo + ((size_t)c * ROWSP + bm) * 128;
            const char* bh = (const char*)Bhi + ((size_t)c * NB + n0) * 128;
            const char* bl = (const char*)Blo + ((size_t)c * NB + n0) * 128;
            BULK_G2S(base,               ah, 16384, mb);
            BULK_G2S(base + 16384,       al, 16384, mb);
            BULK_G2S(base + 32768,       bh, BNB,   mb);
            BULK_G2S(base + 32768 + BNB, bl, BNB,   mb);
        }
    }

    // per-thread ldmatrix address components
    const int arow = lane & 15;
    const int akb = (lane >> 4) << 3;                       // +0 or +8 in k
    const uint32_t aRowOff = (uint32_t)(wm * WR + arow) * 128;
    const uint32_t aSw = (uint32_t)(arow & 7) << 4;
    const int brow = (lane & 7) + ((lane >> 4) << 3);
    const int bkb = ((lane >> 3) & 1) << 3;
    const uint32_t bRowOff = (uint32_t)(wn * WC + brow) * 128;
    const uint32_t bSw = (uint32_t)(brow & 7) << 4;

    float acc[MT][NT][4];
#pragma unroll
    for (int i = 0; i < MT; ++i)
#pragma unroll
        for (int j = 0; j < NT; ++j)
#pragma unroll
            for (int q = 0; q < 4; ++q) acc[i][j][q] = 0.f;

    for (int c = 0; c < NCHUNK; ++c) {
        const int buf = c & 1;
        mbar_wait(buf ? mb1 : mb0, (uint32_t)(c >> 1) & 1);

        const uint32_t base = sb + 1024 + (uint32_t)buf * BUFB;
        const uint32_t aHiS = base, aLoS = base + 16384;
        const uint32_t bHiS = base + 32768, bLoS = base + 32768 + BNB;

#pragma unroll
        for (int ks = 0; ks < 4; ++ks) {
            uint32_t ah[MT][4], al[MT][4], bh[NT][2], bl[NT][2];
            const uint32_t akByte = ((uint32_t)((ks * 16 + akb) * 2)) ^ aSw;
#pragma unroll
            for (int mt = 0; mt < MT; ++mt) {
                uint32_t o = aRowOff + (uint32_t)mt * 2048 + akByte;
                ldsm4(ah[mt], aHiS + o);
                ldsm4(al[mt], aLoS + o);
            }
            const uint32_t bkByte = ((uint32_t)((ks * 16 + bkb) * 2)) ^ bSw;
#pragma unroll
            for (int p = 0; p < NT / 2; ++p) {
                uint32_t o = bRowOff + (uint32_t)p * 2048 + bkByte;
                uint32_t t[4];
                ldsm4(t, bHiS + o);
                bh[2 * p][0] = t[0]; bh[2 * p][1] = t[1];
                bh[2 * p + 1][0] = t[2]; bh[2 * p + 1][1] = t[3];
                ldsm4(t, bLoS + o);
                bl[2 * p][0] = t[0]; bl[2 * p][1] = t[1];
                bl[2 * p + 1][0] = t[2]; bl[2 * p + 1][1] = t[3];
            }
#pragma unroll
            for (int mt = 0; mt < MT; ++mt)
#pragma unroll
                for (int nt = 0; nt < NT; ++nt)
                    mma_bf16(acc[mt][nt], ah[mt], bh[nt]);
#pragma unroll
            for (int mt = 0; mt < MT; ++mt)
#pragma unroll
                for (int nt = 0; nt < NT; ++nt)
                    mma_bf16(acc[mt][nt], ah[mt], bl[nt]);
#pragma unroll
            for (int mt = 0; mt < MT; ++mt)
#pragma unroll
                for (int nt = 0; nt < NT; ++nt)
                    mma_bf16(acc[mt][nt], al[mt], bh[nt]);
        }

        __syncthreads();  // all warps done reading this buffer
        if (tid == 0 && c + 2 < NCHUNK) {
            const int cn = c + 2;
            uint32_t mb = buf ? mb1 : mb0;
            MBARRIER_EXPECT_TX(mb, CHUNK_BYTES);
            const char* ah = (const char*)Ahi + ((size_t)cn * ROWSP + bm) * 128;
            const char* al = (const char*)Alo + ((size_t)cn * ROWSP + bm) * 128;
            const char* bh = (const char*)Bhi + ((size_t)cn * NB + n0) * 128;
            const char* bl = (const char*)Blo + ((size_t)cn * NB + n0) * 128;
            BULK_G2S(base,               ah, 16384, mb);
            BULK_G2S(base + 16384,       al, 16384, mb);
            BULK_G2S(base + 32768,       bh, BNB,   mb);
            BULK_G2S(base + 32768 + BNB, bl, BNB,   mb);
        }
    }

    // epilogue: acc -> C with bias (+relu)
    const int r0 = bm + wm * WR + (lane >> 2);
#pragma unroll
    for (int mt = 0; mt < MT; ++mt) {
#pragma unroll
        for (int nt = 0; nt < NT; ++nt) {
            int row = r0 + mt * 16;
            int col = n0 + wn * WC + nt * 8 + (lane & 3) * 2;
            float bv0 = __ldg(bias + col), bv1 = __ldg(bias + col + 1);
            if (row < NN) {
                float2 v;
                v.x = acc[mt][nt][0] + bv0;
                v.y = acc[mt][nt][1] + bv1;
                if (RELU) { v.x = fmaxf(v.x, 0.f); v.y = fmaxf(v.y, 0.f); }
                *(float2*)&C[(size_t)row * NB + col] = v;
            }
            if (row + 8 < NN) {
                float2 v;
                v.x = acc[mt][nt][2] + bv0;
                v.y = acc[mt][nt][3] + bv1;
                if (RELU) { v.x = fmaxf(v.x, 0.f); v.y = fmaxf(v.y, 0.f); }
                *(float2*)&C[(size_t)(row + 8) * NB + col] = v;
            }
        }
    }
    __syncthreads();
    if (tid == 0) { MBARRIER_INVAL(mb0); MBARRIER_INVAL(mb1); }
}

// ---------------- row_ptr build ---------------------------------------------
__global__ void build_row_ptr(const int* __restrict__ erow) {
    int r = blockIdx.x * blockDim.x + threadIdx.x;
    if (r > NN) return;
    int lo = 0, hi = NE;
    while (lo < hi) {
        int mid = (lo + hi) >> 1;
        if (erow[mid] < r) lo = mid + 1; else hi = mid;
    }
    g_rp[r] = lo;
}

// ---------------- fused CSR SpMM + Chebyshev recurrence ---------------------
__global__ void spmm_cheb(const int* __restrict__ ecol, const float* __restrict__ evals,
                          const float* __restrict__ gamma, float* __restrict__ z,
                          int cur, int prev, int nxt, int k, int first) {
    int t = blockIdx.x * blockDim.x + threadIdx.x;
    int row = t >> 4;
    int ch = t & 15;
    if (row >= NN) return;

    const float4* vcur = (const float4*)g_tb[cur];
    int s = g_rp[row];
    int e = g_rp[row + 1];

    float4 acc = make_float4(0.f, 0.f, 0.f, 0.f);
    int i = s;
    int nb = (e - s) >> 2;
    for (int b = 0; b < nb; ++b, i += 4) {
        int c0 = __ldg(ecol + i + 0), c1 = __ldg(ecol + i + 1);
        int c2 = __ldg(ecol + i + 2), c3 = __ldg(ecol + i + 3);
        float w0 = __ldg(evals + i + 0), w1 = __ldg(evals + i + 1);
        float w2 = __ldg(evals + i + 2), w3 = __ldg(evals + i + 3);
        float4 v0 = __ldg(vcur + (size_t)c0 * 16 + ch);
        float4 v1 = __ldg(vcur + (size_t)c1 * 16 + ch);
        float4 v2 = __ldg(vcur + (size_t)c2 * 16 + ch);
        float4 v3 = __ldg(vcur + (size_t)c3 * 16 + ch);
        acc.x = fmaf(w0, v0.x, acc.x); acc.y = fmaf(w0, v0.y, acc.y);
        acc.z = fmaf(w0, v0.z, acc.z); acc.w = fmaf(w0, v0.w, acc.w);
        acc.x = fmaf(w1, v1.x, acc.x); acc.y = fmaf(w1, v1.y, acc.y);
        acc.z = fmaf(w1, v1.z, acc.z); acc.w = fmaf(w1, v1.w, acc.w);
        acc.x = fmaf(w2, v2.x, acc.x); acc.y = fmaf(w2, v2.y, acc.y);
        acc.z = fmaf(w2, v2.z, acc.z); acc.w = fmaf(w2, v2.w, acc.w);
        acc.x = fmaf(w3, v3.x, acc.x); acc.y = fmaf(w3, v3.y, acc.y);
        acc.z = fmaf(w3, v3.z, acc.z); acc.w = fmaf(w3, v3.w, acc.w);
    }
    for (; i < e; ++i) {
        int col = __ldg(ecol + i);
        float w = __ldg(evals + i);
        float4 v = __ldg(vcur + (size_t)col * 16 + ch);
        acc.x = fmaf(w, v.x, acc.x);
        acc.y = fmaf(w, v.y, acc.y);
        acc.z = fmaf(w, v.z, acc.z);
        acc.w = fmaf(w, v.w, acc.w);
    }

    size_t o = (size_t)row * 16 + ch;
    float4* vnext = (float4*)g_tb[nxt];
    float4* z4 = (float4*)z;

    if (first) {
        float g0 = gamma[0], g1 = gamma[1];
        float4 h = vcur[o];
        vnext[o] = acc;
        float4 zz;
        zz.x = g0 * h.x + g1 * acc.x;
        zz.y = g0 * h.y + g1 * acc.y;
        zz.z = g0 * h.z + g1 * acc.z;
        zz.w = g0 * h.w + g1 * acc.w;
        z4[o] = zz;
    } else {
        const float4* vprev = (const float4*)g_tb[prev];
        float4 p = vprev[o];
        float4 tn;
        tn.x = 2.f * acc.x - p.x;
        tn.y = 2.f * acc.y - p.y;
        tn.z = 2.f * acc.z - p.z;
        tn.w = 2.f * acc.w - p.w;
        vnext[o] = tn;
        float g = gamma[k];
        float4 zz = z4[o];
        zz.x = fmaf(g, tn.x, zz.x);
        zz.y = fmaf(g, tn.y, zz.y);
        zz.z = fmaf(g, tn.z, zz.z);
        zz.w = fmaf(g, tn.w, zz.w);
        z4[o] = zz;
    }
}

// ---------------- launch ----------------------------------------------------
extern "C" void kernel_launch(void* const* d_in, const int* in_sizes, int n_in,
                              void* d_out, int out_size) {
    const float* x     = (const float*)d_in[0];
    const int*   erow  = (const int*)d_in[1];
    const int*   ecol  = (const int*)d_in[2];
    const float* evals = (const float*)d_in[3];
    const float* W1    = (const float*)d_in[4];
    const float* b1    = (const float*)d_in[5];
    const float* W2    = (const float*)d_in[6];
    const float* b2    = (const float*)d_in[7];
    const float* gamma = (const float*)d_in[8];
    float* z = (float*)d_out;

    float *h1, *tb0;
    __nv_bfloat16 *ahi, *alo, *w1hi, *w1lo, *w2hi, *w2lo;
    cudaGetSymbolAddress((void**)&h1, g_h1);
    cudaGetSymbolAddress((void**)&tb0, g_tb);
    cudaGetSymbolAddress((void**)&ahi, g_ahi);
    cudaGetSymbolAddress((void**)&alo, g_alo);
    cudaGetSymbolAddress((void**)&w1hi, g_w1hi);
    cudaGetSymbolAddress((void**)&w1lo, g_w1lo);
    cudaGetSymbolAddress((void**)&w2hi, g_w2hi);
    cudaGetSymbolAddress((void**)&w2lo, g_w2lo);

    // dynamic smem: 1024 + 2 * (32768 + 2*BN*128)
    constexpr int SMEM1 = 1024 + 2 * (32768 + 2 * 128 * 128);  // 132096
    constexpr int SMEM2 = 1024 + 2 * (32768 + 2 * 64 * 128);   // 99328
    cudaFuncSetAttribute(tc_gemm<128, 8, 2, 4, true>,
                         cudaFuncAttributeMaxDynamicSharedMemorySize, SMEM1);
    cudaFuncSetAttribute(tc_gemm<64, 4, 4, 2, false>,
                         cudaFuncAttributeMaxDynamicSharedMemorySize, SMEM2);

    const int MTILES = (NN + 127) / 128;  // 782

    // weight prep (cheap)
    prep_w<8><<<(IND * HID + 255) / 256, 256>>>(W1, IND, w1hi, w1lo);
    prep_w<6><<<(HID * NC + 255) / 256, 256>>>(W2, HID, w2hi, w2lo);

    // A prep for GEMM1: x -> split bf16 chunk planes
    {
        long long tot = (long long)NN * IND;
        prep_a<9><<<(unsigned)((tot + 255) / 256), 256>>>(x, ahi, alo);
    }
    // GEMM1: h1 = relu(x@W1 + b1)   [NN, 256]
    {
        dim3 grid(MTILES, 2);
        tc_gemm<128, 8, 2, 4, true><<<grid, 256, SMEM1>>>(ahi, alo, w1hi, w1lo, b1, h1, HID);
    }
    // A prep for GEMM2: h1 -> split bf16 chunk planes (reuse buffers)
    {
        long long tot = (long long)NN * HID;
        prep_a<8><<<(unsigned)((tot + 255) / 256), 256>>>(h1, ahi, alo);
    }
    // GEMM2: h = h1@W2 + b2 -> g_tb[0]   [NN, 64]
    {
        dim3 grid(MTILES, 1);
        tc_gemm<64, 4, 4, 2, false><<<grid, 256, SMEM2>>>(ahi, alo, w2hi, w2lo, b2, tb0, NC);
    }

    // CSR row_ptr
    build_row_ptr<<<(NN + 256) / 256, 256>>>(erow);

    // Chebyshev chain (8 SpMMs, fused recurrence + z accumulation)
    const int SPMM_BLOCKS = (NN * 16 + 255) / 256;
    spmm_cheb<<<SPMM_BLOCKS, 256>>>(ecol, evals, gamma, z, 0, 0, 1, 1, 1);
    int p = 0, c = 1;
    for (int k = 2; k <= 8; ++k) {
        int n = 3 - p - c;
        spmm_cheb<<<SPMM_BLOCKS, 256>>>(ecol, evals, gamma, z, c, p, n, k, 0);
        p = c; c = n;
    }
}

// round 6
// speedup vs baseline: 1.6270x; 1.1516x over previous
#include <cuda_runtime.h>
#include <cuda_bf16.h>
#include <cstdint>

#define NN 100000
#define ROWSP 100096           // NN padded to multiple of 128
#define NE 3200000
#define IND 512
#define HID 256
#define NC  64

// ---------------- scratch (static device globals; no runtime allocation) ----
__device__ float g_tb[3][(size_t)NN * NC];                     // rotating T_k buffers
__device__ int   g_rp[NN + 1];                                 // CSR row_ptr
// A operand chunk-plane layout: [K/64 planes][ROWSP rows][64] bf16, SW128-swizzled
// per 128B row. x-split (8 planes) for GEMM1.
__device__ __align__(128) __nv_bfloat16 g_ahi[(size_t)8 * ROWSP * 64];
__device__ __align__(128) __nv_bfloat16 g_alo[(size_t)8 * ROWSP * 64];
// h-split (4 planes) written by GEMM1 epilogue, consumed by GEMM2
__device__ __align__(128) __nv_bfloat16 g_hhi[(size_t)4 * ROWSP * 64];
__device__ __align__(128) __nv_bfloat16 g_hlo[(size_t)4 * ROWSP * 64];
// W operands, chunk-tiled [K/64][N][64] bf16 swizzled
__device__ __align__(128) __nv_bfloat16 g_w1hi[8 * 256 * 64], g_w1lo[8 * 256 * 64];
__device__ __align__(128) __nv_bfloat16 g_w2hi[4 * 64 * 64],  g_w2lo[4 * 64 * 64];

// ---------------- inline PTX helpers (base ISA only) ------------------------
__device__ __forceinline__ uint32_t smem_u32(const void* p) {
    uint32_t a;
    asm("{ .reg .u64 t; cvta.to.shared.u64 t, %1; cvt.u32.u64 %0, t; }" : "=r"(a) : "l"(p));
    return a;
}
#define MBARRIER_INIT(addr, cnt) \
    asm volatile("mbarrier.init.shared.b64 [%0], %1;" :: "r"(addr), "r"((uint32_t)(cnt)) : "memory")
#define MBARRIER_INVAL(addr) \
    asm volatile("mbarrier.inval.shared.b64 [%0];" :: "r"(addr) : "memory")
#define MBARRIER_EXPECT_TX(addr, bytes) \
    asm volatile("mbarrier.arrive.expect_tx.shared.b64 _, [%0], %1;" :: "r"(addr), "r"((uint32_t)(bytes)) : "memory")
__device__ __forceinline__ void mbar_wait(uint32_t mbar, uint32_t parity) {
    asm volatile(
        "{\n\t.reg .pred P1;\n\t"
        "WAIT_LOOP_%=:\n\t"
        "mbarrier.try_wait.parity.acquire.cta.shared::cta.b64 P1, [%0], %1, 0x989680;\n\t"
        "@P1 bra.uni WAIT_DONE_%=;\n\t"
        "bra.uni WAIT_LOOP_%=;\n\t"
        "WAIT_DONE_%=:\n\t}"
        :: "r"(mbar), "r"(parity) : "memory");
}
#define BULK_G2S(dst, src, bytes, mbar) \
    asm volatile("cp.async.bulk.shared::cta.global.mbarrier::complete_tx::bytes [%0], [%1], %2, [%3];" \
        :: "r"((uint32_t)(dst)), "l"(src), "r"((uint32_t)(bytes)), "r"((uint32_t)(mbar)) : "memory")

__device__ __forceinline__ void ldsm4(uint32_t* r, uint32_t addr) {
    asm volatile("ldmatrix.sync.aligned.m8n8.x4.shared.b16 {%0,%1,%2,%3}, [%4];"
        : "=r"(r[0]), "=r"(r[1]), "=r"(r[2]), "=r"(r[3]) : "r"(addr));
}
__device__ __forceinline__ void mma_bf16(float* d, const uint32_t* a, const uint32_t* b) {
    asm volatile("mma.sync.aligned.m16n8k16.row.col.f32.bf16.bf16.f32 "
        "{%0,%1,%2,%3}, {%4,%5,%6,%7}, {%8,%9}, {%0,%1,%2,%3};"
        : "+f"(d[0]), "+f"(d[1]), "+f"(d[2]), "+f"(d[3])
        : "r"(a[0]), "r"(a[1]), "r"(a[2]), "r"(a[3]), "r"(b[0]), "r"(b[1]));
}

// ---------------- prep kernels ----------------------------------------------
// Vectorized A prep: one thread = 8 consecutive k of one row (16B hi + 16B lo out).
template <int KSHIFT>
__global__ void prep_a(const float* __restrict__ src,
                       __nv_bfloat16* __restrict__ dhi, __nv_bfloat16* __restrict__ dlo) {
    constexpr int K = 1 << KSHIFT;
    constexpr int G = K / 8;                    // 8-wide groups per row
    long long idx = (long long)blockIdx.x * blockDim.x + threadIdx.x;
    if (idx >= (long long)NN * G) return;
    int r = (int)(idx / G);
    int g = (int)(idx % G);
    int k = g * 8;
    int c = k >> 6, kk = k & 63;

    const float4* s4 = (const float4*)(src + (size_t)r * K + k);
    float4 v0 = s4[0], v1 = s4[1];
    float f[8] = {v0.x, v0.y, v0.z, v0.w, v1.x, v1.y, v1.z, v1.w};
    __nv_bfloat162 hi[4], lo[4];
#pragma unroll
    for (int i = 0; i < 4; ++i) {
        __nv_bfloat16 h0 = __float2bfloat16(f[2 * i]);
        __nv_bfloat16 h1 = __float2bfloat16(f[2 * i + 1]);
        hi[i] = __nv_bfloat162(h0, h1);
        lo[i] = __nv_bfloat162(__float2bfloat16(f[2 * i] - __bfloat162float(h0)),
                               __float2bfloat16(f[2 * i + 1] - __bfloat162float(h1)));
    }
    uint32_t off = (uint32_t)r * 128 + (((uint32_t)kk * 2) ^ (((uint32_t)r & 7) << 4));
    size_t pbase = (size_t)c * ROWSP * 128;
    *(uint4*)((char*)dhi + pbase + off) = *(uint4*)hi;
    *(uint4*)((char*)dlo + pbase + off) = *(uint4*)lo;
}

// W layout: B[n][k] = W[k*N + n]; plane c, row n, perm (kk*2) ^ ((n&7)<<4)
template <int NSHIFT>
__global__ void prep_w(const float* __restrict__ src, int K,
                       __nv_bfloat16* __restrict__ dhi, __nv_bfloat16* __restrict__ dlo) {
    constexpr int N = 1 << NSHIFT;
    int idx = blockIdx.x * blockDim.x + threadIdx.x;
    if (idx >= K * N) return;
    int k = idx >> NSHIFT;
    int n = idx & (N - 1);
    int c = k >> 6, kk = k & 63;
    float v = src[idx];
    __nv_bfloat16 hi = __float2bfloat16(v);
    __nv_bfloat16 lo = __float2bfloat16(v - __bfloat162float(hi));
    int poff = (kk << 1) ^ ((n & 7) << 4);
    size_t dst = ((size_t)c * N + n) * 64 + (poff >> 1);
    dhi[dst] = hi;
    dlo[dst] = lo;
}

// ---------------- split-bf16 mma.sync GEMM, 3-stage pipeline ----------------
// D[128, BN] tile = A[128, K] @ B[BN, K]^T. 3 split products per 64-chunk.
// SPLIT_OUT: relu(acc+bias) written as swizzled bf16 hi/lo chunk planes (for GEMM2).
// else:      acc+bias written fp32 row-major (stride NB).
template <int BN, int NCHUNK, int WM, int WN, bool SPLIT_OUT>
__global__ void __launch_bounds__(256)
tc_gemm(const __nv_bfloat16* __restrict__ Ahi, const __nv_bfloat16* __restrict__ Alo,
        const __nv_bfloat16* __restrict__ Bhi, const __nv_bfloat16* __restrict__ Blo,
        const float* __restrict__ bias, float* __restrict__ C,
        __nv_bfloat16* __restrict__ Ohi, __nv_bfloat16* __restrict__ Olo, int NB) {
    constexpr int WR = 128 / WM;
    constexpr int WC = BN / WN;
    constexpr int MT = WR / 16;
    constexpr int NT = WC / 8;
    constexpr uint32_t BNB = BN * 128;
    constexpr uint32_t BUFB = 32768 + 2 * BNB;

    extern __shared__ char smem[];
    const uint32_t sb = smem_u32(smem);
    const int tid = threadIdx.x;
    const int lane = tid & 31;
    const int wid = tid >> 5;
    const int wm = wid / WN, wn = wid % WN;
    const int bm = blockIdx.y * 128;            // m tile (slow dim)
    const int n0 = blockIdx.x * BN;             // n tile (fast dim -> A L2 reuse)

    if (tid == 0) {
        MBARRIER_INIT(sb + 8, 1);
        MBARRIER_INIT(sb + 24, 1);
        MBARRIER_INIT(sb + 40, 1);
    }
    __syncthreads();

    auto issue = [&](int c) {
        int buf = c % 3;
        uint32_t mb = sb + 8 + (uint32_t)buf * 16;
        uint32_t base = sb + 1024 + (uint32_t)buf * BUFB;
        MBARRIER_EXPECT_TX(mb, BUFB);
        const char* ah = (const char*)Ahi + ((size_t)c * ROWSP + bm) * 128;
        const char* al = (const char*)Alo + ((size_t)c * ROWSP + bm) * 128;
        const char* bh = (const char*)Bhi + ((size_t)c * NB + n0) * 128;
        const char* bl = (const char*)Blo + ((size_t)c * NB + n0) * 128;
        BULK_G2S(base,               ah, 16384, mb);
        BULK_G2S(base + 16384,       al, 16384, mb);
        BULK_G2S(base + 32768,       bh, BNB,   mb);
        BULK_G2S(base + 32768 + BNB, bl, BNB,   mb);
    };
    if (tid == 0) {
#pragma unroll
        for (int c = 0; c < 3 && c < NCHUNK; ++c) issue(c);
    }

    // ldmatrix address components
    const int arow = lane & 15;
    const int akb = (lane >> 4) << 3;
    const uint32_t aRowOff = (uint32_t)(wm * WR + arow) * 128;
    const uint32_t aSw = (uint32_t)(arow & 7) << 4;
    const int brow = (lane & 7) + ((lane >> 4) << 3);
    const int bkb = ((lane >> 3) & 1) << 3;
    const uint32_t bRowOff = (uint32_t)(wn * WC + brow) * 128;
    const uint32_t bSw = (uint32_t)(brow & 7) << 4;

    float acc[MT][NT][4];
#pragma unroll
    for (int i = 0; i < MT; ++i)
#pragma unroll
        for (int j = 0; j < NT; ++j)
#pragma unroll
            for (int q = 0; q < 4; ++q) acc[i][j][q] = 0.f;

    for (int c = 0; c < NCHUNK; ++c) {
        const int buf = c % 3;
        mbar_wait(sb + 8 + (uint32_t)buf * 16, (uint32_t)(c / 3) & 1);

        const uint32_t base = sb + 1024 + (uint32_t)buf * BUFB;
        const uint32_t aHiS = base, aLoS = base + 16384;
        const uint32_t bHiS = base + 32768, bLoS = base + 32768 + BNB;

#pragma unroll
        for (int ks = 0; ks < 4; ++ks) {
            uint32_t ah[MT][4], al[MT][4], bh[NT][2], bl[NT][2];
            const uint32_t akByte = ((uint32_t)((ks * 16 + akb) * 2)) ^ aSw;
#pragma unroll
            for (int mt = 0; mt < MT; ++mt) {
                uint32_t o = aRowOff + (uint32_t)mt * 2048 + akByte;
                ldsm4(ah[mt], aHiS + o);
                ldsm4(al[mt], aLoS + o);
            }
            const uint32_t bkByte = ((uint32_t)((ks * 16 + bkb) * 2)) ^ bSw;
#pragma unroll
            for (int p = 0; p < NT / 2; ++p) {
                uint32_t o = bRowOff + (uint32_t)p * 2048 + bkByte;
                uint32_t t[4];
                ldsm4(t, bHiS + o);
                bh[2 * p][0] = t[0]; bh[2 * p][1] = t[1];
                bh[2 * p + 1][0] = t[2]; bh[2 * p + 1][1] = t[3];
                ldsm4(t, bLoS + o);
                bl[2 * p][0] = t[0]; bl[2 * p][1] = t[1];
                bl[2 * p + 1][0] = t[2]; bl[2 * p + 1][1] = t[3];
            }
#pragma unroll
            for (int mt = 0; mt < MT; ++mt)
#pragma unroll
                for (int nt = 0; nt < NT; ++nt)
                    mma_bf16(acc[mt][nt], ah[mt], bh[nt]);
#pragma unroll
            for (int mt = 0; mt < MT; ++mt)
#pragma unroll
                for (int nt = 0; nt < NT; ++nt)
                    mma_bf16(acc[mt][nt], ah[mt], bl[nt]);
#pragma unroll
            for (int mt = 0; mt < MT; ++mt)
#pragma unroll
                for (int nt = 0; nt < NT; ++nt)
                    mma_bf16(acc[mt][nt], al[mt], bh[nt]);
        }
        __syncthreads();                 // all warps finished reading buf
        if (tid == 0 && c + 3 < NCHUNK) issue(c + 3);
    }

    // epilogue
    const int r0 = bm + wm * WR + (lane >> 2);
#pragma unroll
    for (int mt = 0; mt < MT; ++mt) {
#pragma unroll
        for (int nt = 0; nt < NT; ++nt) {
            int row = r0 + mt * 16;
            int col = n0 + wn * WC + nt * 8 + (lane & 3) * 2;
            float bv0 = __ldg(bias + col), bv1 = __ldg(bias + col + 1);
            if (SPLIT_OUT) {
                int pl = col >> 6, kk = col & 63;
                size_t pbase = (size_t)pl * ROWSP * 128;
                uint32_t xoff = ((uint32_t)kk * 2);
#pragma unroll
                for (int half = 0; half < 2; ++half) {
                    int r = row + half * 8;
                    if (r >= NN) continue;
                    float v0 = fmaxf(acc[mt][nt][2 * half + 0] + bv0, 0.f);
                    float v1 = fmaxf(acc[mt][nt][2 * half + 1] + bv1, 0.f);
                    __nv_bfloat16 h0 = __float2bfloat16(v0);
                    __nv_bfloat16 h1 = __float2bfloat16(v1);
                    __nv_bfloat162 hv(h0, h1);
                    __nv_bfloat162 lv(__float2bfloat16(v0 - __bfloat162float(h0)),
                                      __float2bfloat16(v1 - __bfloat162float(h1)));
                    uint32_t off = (uint32_t)r * 128 + (xoff ^ (((uint32_t)r & 7) << 4));
                    *(__nv_bfloat162*)((char*)Ohi + pbase + off) = hv;
                    *(__nv_bfloat162*)((char*)Olo + pbase + off) = lv;
                }
            } else {
#pragma unroll
                for (int half = 0; half < 2; ++half) {
                    int r = row + half * 8;
                    if (r >= NN) continue;
                    float2 v;
                    v.x = acc[mt][nt][2 * half + 0] + bv0;
                    v.y = acc[mt][nt][2 * half + 1] + bv1;
                    *(float2*)&C[(size_t)r * NB + col] = v;
                }
            }
        }
    }
    __syncthreads();
    if (tid == 0) { MBARRIER_INVAL(sb + 8); MBARRIER_INVAL(sb + 24); MBARRIER_INVAL(sb + 40); }
}

// ---------------- row_ptr build ---------------------------------------------
__global__ void build_row_ptr(const int* __restrict__ erow) {
    int r = blockIdx.x * blockDim.x + threadIdx.x;
    if (r > NN) return;
    int lo = 0, hi = NE;
    while (lo < hi) {
        int mid = (lo + hi) >> 1;
        if (erow[mid] < r) lo = mid + 1; else hi = mid;
    }
    g_rp[r] = lo;
}

// ---------------- fused CSR SpMM + Chebyshev recurrence ---------------------
__global__ void spmm_cheb(const int* __restrict__ ecol, const float* __restrict__ evals,
                          const float* __restrict__ gamma, float* __restrict__ z,
                          int cur, int prev, int nxt, int k, int first, int last) {
    int t = blockIdx.x * blockDim.x + threadIdx.x;
    int row = t >> 4;
    int ch = t & 15;
    if (row >= NN) return;

    const float4* vcur = (const float4*)g_tb[cur];
    int s = g_rp[row];
    int e = g_rp[row + 1];

    float4 acc = make_float4(0.f, 0.f, 0.f, 0.f);
    int i = s;
    int nb = (e - s) >> 2;
    for (int b = 0; b < nb; ++b, i += 4) {
        int c0 = __ldg(ecol + i + 0), c1 = __ldg(ecol + i + 1);
        int c2 = __ldg(ecol + i + 2), c3 = __ldg(ecol + i + 3);
        float w0 = __ldg(evals + i + 0), w1 = __ldg(evals + i + 1);
        float w2 = __ldg(evals + i + 2), w3 = __ldg(evals + i + 3);
        float4 v0 = __ldg(vcur + (size_t)c0 * 16 + ch);
        float4 v1 = __ldg(vcur + (size_t)c1 * 16 + ch);
        float4 v2 = __ldg(vcur + (size_t)c2 * 16 + ch);
        float4 v3 = __ldg(vcur + (size_t)c3 * 16 + ch);
        acc.x = fmaf(w0, v0.x, acc.x); acc.y = fmaf(w0, v0.y, acc.y);
        acc.z = fmaf(w0, v0.z, acc.z); acc.w = fmaf(w0, v0.w, acc.w);
        acc.x = fmaf(w1, v1.x, acc.x); acc.y = fmaf(w1, v1.y, acc.y);
        acc.z = fmaf(w1, v1.z, acc.z); acc.w = fmaf(w1, v1.w, acc.w);
        acc.x = fmaf(w2, v2.x, acc.x); acc.y = fmaf(w2, v2.y, acc.y);
        acc.z = fmaf(w2, v2.z, acc.z); acc.w = fmaf(w2, v2.w, acc.w);
        acc.x = fmaf(w3, v3.x, acc.x); acc.y = fmaf(w3, v3.y, acc.y);
        acc.z = fmaf(w3, v3.z, acc.z); acc.w = fmaf(w3, v3.w, acc.w);
    }
    for (; i < e; ++i) {
        int col = __ldg(ecol + i);
        float w = __ldg(evals + i);
        float4 v = __ldg(vcur + (size_t)col * 16 + ch);
        acc.x = fmaf(w, v.x, acc.x);
        acc.y = fmaf(w, v.y, acc.y);
        acc.z = fmaf(w, v.z, acc.z);
        acc.w = fmaf(w, v.w, acc.w);
    }

    size_t o = (size_t)row * 16 + ch;
    float4* vnext = (float4*)g_tb[nxt];
    float4* z4 = (float4*)z;

    if (first) {
        float g0 = gamma[0], g1 = gamma[1];
        float4 h = vcur[o];
        vnext[o] = acc;
        float4 zz;
        zz.x = g0 * h.x + g1 * acc.x;
        zz.y = g0 * h.y + g1 * acc.y;
        zz.z = g0 * h.z + g1 * acc.z;
        zz.w = g0 * h.w + g1 * acc.w;
        z4[o] = zz;
    } else {
        const float4* vprev = (const float4*)g_tb[prev];
        float4 p = vprev[o];
        float4 tn;
        tn.x = 2.f * acc.x - p.x;
        tn.y = 2.f * acc.y - p.y;
        tn.z = 2.f * acc.z - p.z;
        tn.w = 2.f * acc.w - p.w;
        if (!last) vnext[o] = tn;
        float g = gamma[k];
        float4 zz = z4[o];
        zz.x = fmaf(g, tn.x, zz.x);
        zz.y = fmaf(g, tn.y, zz.y);
        zz.z = fmaf(g, tn.z, zz.z);
        zz.w = fmaf(g, tn.w, zz.w);
        z4[o] = zz;
    }
}

// ---------------- launch ----------------------------------------------------
extern "C" void kernel_launch(void* const* d_in, const int* in_sizes, int n_in,
                              void* d_out, int out_size) {
    const float* x     = (const float*)d_in[0];
    const int*   erow  = (const int*)d_in[1];
    const int*   ecol  = (const int*)d_in[2];
    const float* evals = (const float*)d_in[3];
    const float* W1    = (const float*)d_in[4];
    const float* b1    = (const float*)d_in[5];
    const float* W2    = (const float*)d_in[6];
    const float* b2    = (const float*)d_in[7];
    const float* gamma = (const float*)d_in[8];
    float* z = (float*)d_out;

    float *tb0;
    __nv_bfloat16 *ahi, *alo, *hhi, *hlo, *w1hi, *w1lo, *w2hi, *w2lo;
    cudaGetSymbolAddress((void**)&tb0, g_tb);
    cudaGetSymbolAddress((void**)&ahi, g_ahi);
    cudaGetSymbolAddress((void**)&alo, g_alo);
    cudaGetSymbolAddress((void**)&hhi, g_hhi);
    cudaGetSymbolAddress((void**)&hlo, g_hlo);
    cudaGetSymbolAddress((void**)&w1hi, g_w1hi);
    cudaGetSymbolAddress((void**)&w1lo, g_w1lo);
    cudaGetSymbolAddress((void**)&w2hi, g_w2hi);
    cudaGetSymbolAddress((void**)&w2lo, g_w2lo);

    // dynamic smem: 1024 + 3 * (32768 + 2*BN*128)
    constexpr int SMEM1 = 1024 + 3 * (32768 + 2 * 128 * 128);  // 197632
    constexpr int SMEM2 = 1024 + 3 * (32768 + 2 * 64 * 128);   // 148480
    cudaFuncSetAttribute(tc_gemm<128, 8, 2, 4, true>,
                         cudaFuncAttributeMaxDynamicSharedMemorySize, SMEM1);
    cudaFuncSetAttribute(tc_gemm<64, 4, 4, 2, false>,
                         cudaFuncAttributeMaxDynamicSharedMemorySize, SMEM2);

    const int MTILES = (NN + 127) / 128;  // 782

    // weight prep (cheap)
    prep_w<8><<<(IND * HID + 255) / 256, 256>>>(W1, IND, w1hi, w1lo);
    prep_w<6><<<(HID * NC + 255) / 256, 256>>>(W2, HID, w2hi, w2lo);

    // A prep for GEMM1 (vectorized): x -> split bf16 chunk planes
    {
        long long tot = (long long)NN * (IND / 8);
        prep_a<9><<<(unsigned)((tot + 255) / 256), 256>>>(x, ahi, alo);
    }
    // GEMM1: relu(x@W1 + b1) -> split bf16 planes (g_hhi/g_hlo), no fp32 h1
    {
        dim3 grid(2, MTILES);   // n fast -> adjacent CTAs reuse A tile in L2
        tc_gemm<128, 8, 2, 4, true><<<grid, 256, SMEM1>>>(
            ahi, alo, w1hi, w1lo, b1, nullptr, hhi, hlo, HID);
    }
    // GEMM2: h@W2 + b2 -> g_tb[0] fp32
    {
        dim3 grid(1, MTILES);
        tc_gemm<64, 4, 4, 2, false><<<grid, 256, SMEM2>>>(
            hhi, hlo, w2hi, w2lo, b2, tb0, nullptr, nullptr, NC);
    }

    // CSR row_ptr
    build_row_ptr<<<(NN + 256) / 256, 256>>>(erow);

    // Chebyshev chain (8 SpMMs, fused recurrence + z accumulation)
    const int SPMM_BLOCKS = (NN * 16 + 255) / 256;
    spmm_cheb<<<SPMM_BLOCKS, 256>>>(ecol, evals, gamma, z, 0, 0, 1, 1, 1, 0);
    int p = 0, c = 1;
    for (int k = 2; k <= 8; ++k) {
        int n = 3 - p - c;
        spmm_cheb<<<SPMM_BLOCKS, 256>>>(ecol, evals, gamma, z, c, p, n, k, 0, k == 8);
        p = c; c = n;
    }
}